// round 1
// baseline (speedup 1.0000x reference)
#include <cuda_runtime.h>
#include <cuda_bf16.h>
#include <cstdint>

// Problem constants (from reference)
#define BATCH    16384
#define IN_SIZE  448
#define OUT_SIZE 448
#define W_TOT    14336
#define NE       64
#define NB       32          // nodes per compute tile
#define NTHREADS 256

// Segment table:
// s0: mi=96, mo=96, d=1, xoff=0,   woff=0,     yoff=0
// s1: mi=64, mo=64, d=3, xoff=96,  woff=9216,  yoff=96
// s2: mi=32, mo=32, d=5, xoff=288, woff=13312, yoff=288

// Device scratch (allocation-free rule: use __device__ globals)
__device__ int g_is64;
__device__ int g_count[NE];
__device__ int g_cursor[NE];
__device__ int g_offset[NE + 1];
__device__ int g_perm[BATCH];

__device__ __forceinline__ int get_idx(const void* p, int b, int is64) {
    if (is64) return (int)((const long long*)p)[b];
    return ((const int*)p)[b];
}

// ---------------------------------------------------------------------------
// Pass 0: detect index dtype (int32 vs int64) + zero counters
// ---------------------------------------------------------------------------
__global__ void init_kernel(const void* idxp) {
    int t = threadIdx.x;
    if (t < NE) { g_count[t] = 0; g_cursor[t] = 0; }
    if (t == 0) {
        // If data is int32 (values 0..63), pairs reinterpreted as int64 are
        // v0 + (v1<<32) which is >=64 unless v1==0; over 256 samples the
        // all-zero-odd case has probability ~(1/64)^256 ~ 0.
        const long long* p = (const long long*)idxp;
        int is64 = 1;
        for (int i = 0; i < 256; i++) {
            long long v = p[i];
            if (v < 0ll || v >= 64ll) { is64 = 0; break; }
        }
        g_is64 = is64;
    }
}

// ---------------------------------------------------------------------------
// Pass 1: histogram of elements
// ---------------------------------------------------------------------------
__global__ void hist_kernel(const void* idxp) {
    __shared__ int h[NE];
    int tid = threadIdx.x;
    if (tid < NE) h[tid] = 0;
    __syncthreads();
    int is64 = g_is64;
    int b = blockIdx.x * NTHREADS + tid;
    int e = get_idx(idxp, b, is64);
    atomicAdd(&h[e], 1);
    __syncthreads();
    if (tid < NE) atomicAdd(&g_count[tid], h[tid]);
}

// ---------------------------------------------------------------------------
// Pass 2: exclusive scan (tiny, 64 bins)
// ---------------------------------------------------------------------------
__global__ void scan_kernel() {
    int s = 0;
    for (int e = 0; e < NE; e++) { g_offset[e] = s; s += g_count[e]; }
    g_offset[NE] = s;
}

// ---------------------------------------------------------------------------
// Pass 3: scatter node ids into element-sorted permutation
// (order within an element is arbitrary; per-node outputs are independent,
//  so the final result is deterministic)
// ---------------------------------------------------------------------------
__global__ void scatter_kernel(const void* idxp) {
    int b = blockIdx.x * NTHREADS + threadIdx.x;
    int e = get_idx(idxp, b, g_is64);
    int pos = g_offset[e] + atomicAdd(&g_cursor[e], 1);
    g_perm[pos] = b;
}

// ---------------------------------------------------------------------------
// Compute: per-segment register-tiled SIMT GEMM with W + x + y staged in SMEM
// ---------------------------------------------------------------------------
// SMEM layout (floats):
//   sW : W_TOT (14336)            -- full weight slice of current element
//   sX : NB * 193 (padded rows)   -- max segment x row is 192 (seg1)
//   sY : NB * 193 (padded rows)   -- max segment y row is 192 (seg1)
#define XROW_PAD 193
#define SMEM_FLOATS (W_TOT + 2 * NB * XROW_PAD)
#define SMEM_BYTES  (SMEM_FLOATS * 4)

template<int MI, int MO, int D, int TNX, int TN, int TNY, int TM,
         int XOFF, int WOFF, int YOFF>
__device__ __forceinline__ void do_seg(
    const float* __restrict__ sW, float* __restrict__ sX, float* __restrict__ sY,
    const float* __restrict__ x, float* __restrict__ y,
    const int* __restrict__ s_node, int R, int tid)
{
    constexpr int LEN  = MI * D;   // x row length for this segment
    constexpr int OLEN = MO * D;   // y row length for this segment
    constexpr int LENP  = LEN + 1;
    constexpr int OLENP = OLEN + 1;
    static_assert(TNX * TNY == NTHREADS, "thread grid");
    static_assert(TNX * TN == MO, "col tiling");
    static_assert(TNY * TM == NB * D, "row tiling");

    // Stage x for NB nodes (zero-fill beyond R so garbage never enters FMAs)
    for (int idx = tid; idx < NB * LEN; idx += NTHREADS) {
        int nb = idx / LEN, off = idx - nb * LEN;
        float v = 0.f;
        if (nb < R) v = x[(size_t)s_node[nb] * IN_SIZE + XOFF + off];
        sX[nb * LENP + off] = v;
    }
    __syncthreads();

    const int tx = tid % TNX;
    const int ty = tid / TNX;

    float acc[TM][TN];
    #pragma unroll
    for (int a = 0; a < TM; a++)
        #pragma unroll
        for (int j = 0; j < TN; j++) acc[a][j] = 0.f;

    // Precompute per-row smem base: row r -> node nb = r/D, comp m = r%D
    int xbase[TM];
    #pragma unroll
    for (int a = 0; a < TM; a++) {
        int r = ty * TM + a;
        int nb = r / D, m = r - nb * D;
        xbase[a] = nb * LENP + m;
    }

    #pragma unroll 4
    for (int k = 0; k < MI; k++) {
        float wv[TN];
        #pragma unroll
        for (int j = 0; j < TN; j++)
            wv[j] = sW[WOFF + k * MO + tx + TNX * j];
        #pragma unroll
        for (int a = 0; a < TM; a++) {
            float xv = sX[xbase[a] + k * D];
            #pragma unroll
            for (int j = 0; j < TN; j++)
                acc[a][j] = fmaf(xv, wv[j], acc[a][j]);
        }
    }

    // Stage y (padded rows keep banks spread)
    #pragma unroll
    for (int a = 0; a < TM; a++) {
        int r = ty * TM + a;
        int nb = r / D, m = r - nb * D;
        #pragma unroll
        for (int j = 0; j < TN; j++) {
            int o = tx + TNX * j;
            sY[nb * OLENP + o * D + m] = acc[a][j];
        }
    }
    __syncthreads();

    // Coalesced write-out (only valid rows)
    for (int idx = tid; idx < R * OLEN; idx += NTHREADS) {
        int nb = idx / OLEN, off = idx - nb * OLEN;
        y[(size_t)s_node[nb] * OUT_SIZE + YOFF + off] = sY[nb * OLENP + off];
    }
    __syncthreads();
}

__global__ void __launch_bounds__(NTHREADS)
compute_kernel(const float* __restrict__ W, const float* __restrict__ x,
               float* __restrict__ y)
{
    extern __shared__ float smem[];
    float* sW = smem;
    float* sX = smem + W_TOT;
    float* sY = sX + NB * XROW_PAD;
    __shared__ int s_off[NE + 1];
    __shared__ int s_node[NB];

    const int tid = threadIdx.x;
    if (tid < NE + 1) s_off[tid] = g_offset[tid];
    __syncthreads();

    const int p0 = blockIdx.x * NB;
    const int p1 = p0 + NB;

    // Find first element whose bucket intersects [p0, p1)
    int e = 0;
    while (e < NE - 1 && s_off[e + 1] <= p0) e++;

    for (; e < NE && s_off[e] < p1; ++e) {
        int r0 = max(p0, s_off[e]);
        int r1 = min(p1, s_off[e + 1]);
        if (r1 <= r0) continue;
        int R = r1 - r0;

        if (tid < R) s_node[tid] = g_perm[r0 + tid];

        // Stage this element's full weight slice (57 KB) in SMEM
        const float4* Wg4 = (const float4*)(W + (size_t)e * W_TOT);
        float4* sW4 = (float4*)sW;
        for (int i = tid; i < W_TOT / 4; i += NTHREADS) sW4[i] = Wg4[i];
        __syncthreads();

        // seg0: mi=96 mo=96 d=1  -> M=32 rows, N=96 cols. 32x8 threads, 4x3 tile
        do_seg<96, 96, 1, 32, 3, 8, 4, 0, 0, 0>(sW, sX, sY, x, y, s_node, R, tid);
        // seg1: mi=64 mo=64 d=3  -> M=96 rows, N=64 cols. 16x16 threads, 6x4 tile
        do_seg<64, 64, 3, 16, 4, 16, 6, 96, 9216, 96>(sW, sX, sY, x, y, s_node, R, tid);
        // seg2: mi=32 mo=32 d=5  -> M=160 rows, N=32 cols. 8x32 threads, 5x4 tile
        do_seg<32, 32, 5, 8, 4, 32, 5, 288, 13312, 288>(sW, sX, sY, x, y, s_node, R, tid);
        // do_seg ends with __syncthreads() -> safe to reload sW next run
    }
}

// ---------------------------------------------------------------------------
// Launch
// ---------------------------------------------------------------------------
extern "C" void kernel_launch(void* const* d_in, const int* in_sizes, int n_in,
                              void* d_out, int out_size)
{
    const float* W  = (const float*)d_in[0];   // [64, 14336]
    const float* x  = (const float*)d_in[1];   // [16384, 448]
    const void*  ix = d_in[2];                 // [16384] int32 or int64
    float* y = (float*)d_out;                  // [16384, 448]

    cudaFuncSetAttribute(compute_kernel,
                         cudaFuncAttributeMaxDynamicSharedMemorySize, SMEM_BYTES);

    init_kernel<<<1, 64>>>(ix);
    hist_kernel<<<BATCH / NTHREADS, NTHREADS>>>(ix);
    scan_kernel<<<1, 1>>>();
    scatter_kernel<<<BATCH / NTHREADS, NTHREADS>>>(ix);
    compute_kernel<<<BATCH / NB, NTHREADS, SMEM_BYTES>>>(W, x, y);
}

// round 2
// speedup vs baseline: 1.8450x; 1.8450x over previous
#include <cuda_runtime.h>
#include <cuda_bf16.h>
#include <cstdint>

// Problem constants
#define BATCH    16384
#define IN_SIZE  448
#define OUT_SIZE 448
#define W_TOT    14336
#define NE       64
#define NB       64          // nodes per compute tile
#define NTHREADS 256
#define MAX_TILES 320        // <= BATCH/NB + NE

// Device scratch (allocation-free rule)
__device__ int g_is64;
__device__ int g_count[NE];
__device__ int g_cursor[NE];
__device__ int g_offset[NE + 1];
__device__ int g_perm[BATCH];
__device__ int g_ntiles;
__device__ int g_tile_e[MAX_TILES];
__device__ int g_tile_r0[MAX_TILES];

__device__ __forceinline__ int get_idx(const void* p, int b, int is64) {
    if (is64) return (int)((const long long*)p)[b];
    return ((const int*)p)[b];
}

// ---------------------------------------------------------------------------
// Pass 0: detect index dtype (int32 vs int64) + zero counters
// ---------------------------------------------------------------------------
__global__ void init_kernel(const void* idxp) {
    int t = threadIdx.x;
    if (t < NE) { g_count[t] = 0; g_cursor[t] = 0; }
    if (t == 0) {
        const long long* p = (const long long*)idxp;
        int is64 = 1;
        for (int i = 0; i < 256; i++) {
            long long v = p[i];
            if (v < 0ll || v >= 64ll) { is64 = 0; break; }
        }
        g_is64 = is64;
    }
}

// ---------------------------------------------------------------------------
// Pass 1: histogram (smem-aggregated)
// ---------------------------------------------------------------------------
__global__ void hist_kernel(const void* idxp) {
    __shared__ int h[NE];
    int tid = threadIdx.x;
    if (tid < NE) h[tid] = 0;
    __syncthreads();
    int b = blockIdx.x * NTHREADS + tid;
    int e = get_idx(idxp, b, g_is64);
    atomicAdd(&h[e], 1);
    __syncthreads();
    if (tid < NE && h[tid] > 0) atomicAdd(&g_count[tid], h[tid]);
}

// ---------------------------------------------------------------------------
// Pass 2: scan + build bucket-aligned tile list (single block)
// ---------------------------------------------------------------------------
__global__ void scan_tiles_kernel() {
    __shared__ int cnt[NE], offs[NE], toff[NE];
    int t = threadIdx.x;          // 64 threads
    cnt[t] = g_count[t];
    __syncthreads();
    if (t == 0) {
        int s = 0, ts = 0;
        for (int e = 0; e < NE; e++) {
            offs[e] = s; g_offset[e] = s; s += cnt[e];
            toff[e] = ts; ts += (cnt[e] + NB - 1) / NB;
        }
        g_offset[NE] = s;
        g_ntiles = ts;
    }
    __syncthreads();
    int c = cnt[t], base = toff[t], o = offs[t];
    for (int i = 0; i * NB < c; i++) {
        g_tile_e[base + i]  = t;
        g_tile_r0[base + i] = o + i * NB;
    }
}

// ---------------------------------------------------------------------------
// Pass 3: scatter with block-aggregated ranks (few global atomics)
// ---------------------------------------------------------------------------
__global__ void scatter_kernel(const void* idxp) {
    __shared__ int h[NE];
    __shared__ int base[NE];
    int tid = threadIdx.x;
    if (tid < NE) h[tid] = 0;
    __syncthreads();
    int b = blockIdx.x * NTHREADS + tid;
    int e = get_idx(idxp, b, g_is64);
    int rank = atomicAdd(&h[e], 1);           // smem atomic: cheap
    __syncthreads();
    if (tid < NE && h[tid] > 0) base[tid] = atomicAdd(&g_cursor[tid], h[tid]);
    __syncthreads();
    g_perm[g_offset[e] + base[e] + rank] = b;
}

// ---------------------------------------------------------------------------
// Compute: per-segment register-tiled SIMT GEMM, W + staging in SMEM
// ---------------------------------------------------------------------------
// SMEM floats: sW[14336] + shared sXY[NB * (192+4)]
#define ROW_PAD 4
#define XY_FLOATS (NB * (192 + ROW_PAD))
#define SMEM_FLOATS (W_TOT + XY_FLOATS)
#define SMEM_BYTES  (SMEM_FLOATS * 4)

template<int MI, int MO, int D, int TNX, int TN, int TNY, int TM,
         int XOFF, int WOFF, int YOFF>
__device__ __forceinline__ void do_seg(
    const float* __restrict__ sW, float* __restrict__ sXY,
    const float* __restrict__ x, float* __restrict__ y,
    const int* __restrict__ s_node, int R, int tid)
{
    constexpr int LEN   = MI * D;
    constexpr int OLEN  = MO * D;
    constexpr int LENP  = LEN + ROW_PAD;    // multiple of 4
    constexpr int OLENP = OLEN + ROW_PAD;
    constexpr int LEN4  = LEN / 4;
    constexpr int OLEN4 = OLEN / 4;
    static_assert(TNX * TNY == NTHREADS, "thread grid");
    static_assert(TNX * TN == MO, "col tiling");
    static_assert(TNY * TM == NB * D, "row tiling");
    static_assert((LEN % 4) == 0 && (OLEN % 4) == 0, "vec");

    // Stage x (float4), zero-fill beyond R
    for (int idx = tid; idx < NB * LEN4; idx += NTHREADS) {
        int nb = idx / LEN4, o4 = idx - nb * LEN4;
        float4 v = make_float4(0.f, 0.f, 0.f, 0.f);
        if (nb < R)
            v = *(const float4*)(x + (size_t)s_node[nb] * IN_SIZE + XOFF + 4 * o4);
        *(float4*)(sXY + nb * LENP + 4 * o4) = v;
    }
    __syncthreads();

    const int tx = tid % TNX;
    const int ty = tid / TNX;

    float acc[TM][TN];
    #pragma unroll
    for (int a = 0; a < TM; a++)
        #pragma unroll
        for (int j = 0; j < TN; j++) acc[a][j] = 0.f;

    int xbase[TM];
    #pragma unroll
    for (int a = 0; a < TM; a++) {
        int r = ty * TM + a;
        int nb = r / D, m = r - nb * D;
        xbase[a] = nb * LENP + m;
    }

    #pragma unroll 2
    for (int k = 0; k < MI; k++) {
        float wv[TN];
        #pragma unroll
        for (int j = 0; j < TN; j++)
            wv[j] = sW[WOFF + k * MO + tx + TNX * j];
        #pragma unroll
        for (int a = 0; a < TM; a++) {
            float xv = sXY[xbase[a] + k * D];
            #pragma unroll
            for (int j = 0; j < TN; j++)
                acc[a][j] = fmaf(xv, wv[j], acc[a][j]);
        }
    }
    __syncthreads();   // all sXY reads done before overwrite with y

    // Stage y into same buffer
    #pragma unroll
    for (int a = 0; a < TM; a++) {
        int r = ty * TM + a;
        int nb = r / D, m = r - nb * D;
        #pragma unroll
        for (int j = 0; j < TN; j++) {
            int o = tx + TNX * j;
            sXY[nb * OLENP + o * D + m] = acc[a][j];
        }
    }
    __syncthreads();

    // Coalesced vectorized write-out (valid rows only)
    for (int idx = tid; idx < R * OLEN4; idx += NTHREADS) {
        int nb = idx / OLEN4, o4 = idx - nb * OLEN4;
        *(float4*)(y + (size_t)s_node[nb] * OUT_SIZE + YOFF + 4 * o4) =
            *(const float4*)(sXY + nb * OLENP + 4 * o4);
    }
    __syncthreads();
}

__global__ void __launch_bounds__(NTHREADS)
compute_kernel(const float* __restrict__ W, const float* __restrict__ x,
               float* __restrict__ y)
{
    extern __shared__ float smem[];
    float* sW  = smem;
    float* sXY = smem + W_TOT;
    __shared__ int s_node[NB];

    const int t = blockIdx.x;
    if (t >= g_ntiles) return;

    const int tid = threadIdx.x;
    const int e  = g_tile_e[t];
    const int r0 = g_tile_r0[t];
    const int R  = min(NB, g_offset[e + 1] - r0);

    if (tid < R) s_node[tid] = g_perm[r0 + tid];

    // Stage this element's full weight slice (57 KB)
    const float4* Wg4 = (const float4*)(W + (size_t)e * W_TOT);
    float4* sW4 = (float4*)sW;
    #pragma unroll 4
    for (int i = tid; i < W_TOT / 4; i += NTHREADS) sW4[i] = Wg4[i];
    __syncthreads();

    // seg0: mi=96 mo=96 d=1 -> M=64,N=96.  16x16 threads, 4x6 reg tile
    do_seg<96, 96, 1, 16, 6, 16, 4, 0, 0, 0>(sW, sXY, x, y, s_node, R, tid);
    // seg1: mi=64 mo=64 d=3 -> M=192,N=64. 16x16 threads, 12x4 reg tile
    do_seg<64, 64, 3, 16, 4, 16, 12, 96, 9216, 96>(sW, sXY, x, y, s_node, R, tid);
    // seg2: mi=32 mo=32 d=5 -> M=320,N=32. 8x32 threads, 10x4 reg tile
    do_seg<32, 32, 5, 8, 4, 32, 10, 288, 13312, 288>(sW, sXY, x, y, s_node, R, tid);
}

// ---------------------------------------------------------------------------
// Launch
// ---------------------------------------------------------------------------
extern "C" void kernel_launch(void* const* d_in, const int* in_sizes, int n_in,
                              void* d_out, int out_size)
{
    const float* W  = (const float*)d_in[0];   // [64, 14336]
    const float* x  = (const float*)d_in[1];   // [16384, 448]
    const void*  ix = d_in[2];                 // [16384] int32 or int64
    float* y = (float*)d_out;                  // [16384, 448]

    cudaFuncSetAttribute(compute_kernel,
                         cudaFuncAttributeMaxDynamicSharedMemorySize, SMEM_BYTES);

    init_kernel<<<1, 64>>>(ix);
    hist_kernel<<<BATCH / NTHREADS, NTHREADS>>>(ix);
    scan_tiles_kernel<<<1, 64>>>();
    scatter_kernel<<<BATCH / NTHREADS, NTHREADS>>>(ix);
    compute_kernel<<<MAX_TILES, NTHREADS, SMEM_BYTES>>>(W, x, y);
}